// round 5
// baseline (speedup 1.0000x reference)
#include <cuda_runtime.h>
#include <math.h>
#include <stdint.h>

#define BATCH 8
#define CCH 512
#define SS 1024
#define NHD 8
#define HDD 64
#define NGR 32
#define CG 16
#define C8 64
#define C2 256
#define GEPS 1e-6f

// ---------------- static scratch ----------------
__device__ float d_hs   [BATCH*CCH*SS];
__device__ float d_shn  [BATCH*CCH*SS];
__device__ float d_senh [BATCH*CCH*SS];
__device__ float d_a1   [BATCH*C8*SS];
__device__ float d_a2   [BATCH*C8*SS];
__device__ float d_swt  [BATCH*SS];
__device__ float d_q    [BATCH*SS*CCH];
__device__ float d_k    [BATCH*SS*CCH];
__device__ float d_v    [BATCH*SS*CCH];
__device__ float d_qm   [2*BATCH*SS*C2];
__device__ float d_km   [2*BATCH*SS*C2];
__device__ float d_vm   [2*BATCH*SS*C2];
__device__ float d_comb [BATCH*SS*2*CCH];
__device__ float d_f1   [BATCH*SS*CCH];
__device__ float d_fus  [BATCH*SS*CCH];
__device__ float d_fin  [BATCH*SS*CCH];

// ---------------- helpers ----------------
__device__ __forceinline__ float blk_sum(float v, float* sb, int tid) {
    sb[tid] = v; __syncthreads();
    for (int o = 128; o > 0; o >>= 1) { if (tid < o) sb[tid] += sb[tid + o]; __syncthreads(); }
    float r = sb[0]; __syncthreads(); return r;
}
__device__ __forceinline__ float silu_f(float x) { return x / (1.0f + expf(-x)); }
__device__ __forceinline__ float f2tf(float f) {
    uint32_t u; asm("cvt.rna.tf32.f32 %0, %1;" : "=r"(u) : "f"(f));
    return __uint_as_float(u);
}

// ---------------- group norm, channel-major (B,C,S), optional pos add ----------------
__global__ void gn_cmajor(const float* __restrict__ x, const float* __restrict__ g,
                          const float* __restrict__ be, const float* __restrict__ pos,
                          float* __restrict__ y) {
    __shared__ float sb[256];
    int tid = threadIdx.x;
    int b = blockIdx.x / NGR, gi = blockIdx.x % NGR;
    long base = (long)b * CCH * SS + (long)gi * CG * SS;
    float s1 = 0.f, s2 = 0.f;
    for (int i = tid; i < CG * SS; i += 256) { float v = x[base + i]; s1 += v; s2 += v * v; }
    s1 = blk_sum(s1, sb, tid);
    s2 = blk_sum(s2, sb, tid);
    float mu = s1 / (float)(CG * SS);
    float var = s2 / (float)(CG * SS) - mu * mu;
    float inv = rsqrtf(var + GEPS);
    for (int i = tid; i < CG * SS; i += 256) {
        int cl = i >> 10, s = i & 1023;
        int c = gi * CG + cl;
        float v = (x[base + i] - mu) * inv * g[c] + be[c];
        if (pos) v += pos[(long)c * SS + s];
        y[base + i] = v;
    }
}

// ---------------- group norm token-major + residual, out (B,C,S) ----------------
__global__ void gn_post_k(const float* __restrict__ xt, const float* __restrict__ g,
                          const float* __restrict__ be, const float* __restrict__ resid,
                          float* __restrict__ y) {
    __shared__ float sb[256];
    int tid = threadIdx.x;
    int b = blockIdx.x / NGR, gi = blockIdx.x % NGR;
    long tbase = (long)b * SS * CCH + gi * CG;
    float s1 = 0.f, s2 = 0.f;
    for (int i = tid; i < CG * SS; i += 256) {
        int s = i >> 4, cl = i & 15;
        float v = xt[tbase + (long)s * CCH + cl]; s1 += v; s2 += v * v;
    }
    s1 = blk_sum(s1, sb, tid);
    s2 = blk_sum(s2, sb, tid);
    float mu = s1 / (float)(CG * SS);
    float var = s2 / (float)(CG * SS) - mu * mu;
    float inv = rsqrtf(var + GEPS);
    for (int i = tid; i < CG * SS; i += 256) {
        int s = i >> 4, cl = i & 15;
        int c = gi * CG + cl;
        float v = (xt[tbase + (long)s * CCH + cl] - mu) * inv * g[c] + be[c];
        long oidx = (long)b * CCH * SS + (long)c * SS + s;
        y[oidx] = v + resid[oidx];
    }
}

// =====================================================================
// Batched projection GEMM (TN): Y[b] = A[b]^T(channel-major) @ W^T.
// =====================================================================
struct Ptr6 { const float* A[6]; const float* W[6]; float* Y[6]; };

__global__ __launch_bounds__(256) void gemm_proj(Ptr6 ps, int N) {
    __shared__ float smem[32 * 136 + 64 * 36];
    float* As = smem;
    float* Bs = smem + 32 * 136;

    int z = blockIdx.z;
    int which = z >> 3, b = z & 7;
    const float* Ab = ps.A[which] + (long)b * CCH * SS;
    const float* Bb = ps.W[which];
    float*       Yb = ps.Y[which] + (long)b * SS * N;
    int m0 = blockIdx.x * 128, n0 = blockIdx.y * 64;

    int tid = threadIdx.x;
    int w = tid >> 5, lane = tid & 31;
    int wm = w & 3, wn = w >> 2;
    int g = lane >> 2, tig = lane & 3;
    int rbase = wm * 32, cbase = wn * 32;

    float acc[2][4][4];
    #pragma unroll
    for (int i = 0; i < 2; i++)
        #pragma unroll
        for (int j = 0; j < 4; j++)
            #pragma unroll
            for (int l = 0; l < 4; l++) acc[i][j][l] = 0.f;

    float4 aR[4], bR[2];
    int a_mm = (tid & 31) * 4, a_kb = tid >> 5;
    int b_kk = (tid & 7) * 4, b_nb = tid >> 3;

    auto ldg = [&](int k0) {
        #pragma unroll
        for (int it = 0; it < 4; it++)
            aR[it] = *(const float4*)&Ab[(long)(k0 + a_kb + it * 8) * SS + m0 + a_mm];
        #pragma unroll
        for (int it = 0; it < 2; it++)
            bR[it] = *(const float4*)&Bb[(long)(n0 + b_nb + it * 32) * 512 + k0 + b_kk];
    };
    auto sts = [&]() {
        #pragma unroll
        for (int it = 0; it < 4; it++) {
            float4 v = aR[it];
            v.x = f2tf(v.x); v.y = f2tf(v.y); v.z = f2tf(v.z); v.w = f2tf(v.w);
            *(float4*)&As[(a_kb + it * 8) * 136 + a_mm] = v;
        }
        #pragma unroll
        for (int it = 0; it < 2; it++) {
            float4 v = bR[it];
            v.x = f2tf(v.x); v.y = f2tf(v.y); v.z = f2tf(v.z); v.w = f2tf(v.w);
            *(float4*)&Bs[(b_nb + it * 32) * 36 + b_kk] = v;
        }
    };

    ldg(0);
    for (int k0 = 0; k0 < 512; k0 += 32) {
        sts();
        __syncthreads();
        if (k0 + 32 < 512) ldg(k0 + 32);

        #pragma unroll
        for (int ks = 0; ks < 4; ks++) {
            int kk = ks * 8 + tig, kk2 = kk + 4;
            uint32_t af[2][4], bf[4][2];
            #pragma unroll
            for (int mt = 0; mt < 2; mt++) {
                int r = rbase + mt * 16 + g;
                af[mt][0] = __float_as_uint(As[kk  * 136 + r]);
                af[mt][1] = __float_as_uint(As[kk  * 136 + r + 8]);
                af[mt][2] = __float_as_uint(As[kk2 * 136 + r]);
                af[mt][3] = __float_as_uint(As[kk2 * 136 + r + 8]);
            }
            #pragma unroll
            for (int nt = 0; nt < 4; nt++) {
                int cN = cbase + nt * 8 + g;
                bf[nt][0] = __float_as_uint(Bs[cN * 36 + kk]);
                bf[nt][1] = __float_as_uint(Bs[cN * 36 + kk2]);
            }
            #pragma unroll
            for (int mt = 0; mt < 2; mt++)
                #pragma unroll
                for (int nt = 0; nt < 4; nt++) {
                    asm volatile(
                        "mma.sync.aligned.m16n8k8.row.col.f32.tf32.tf32.f32 "
                        "{%0,%1,%2,%3},{%4,%5,%6,%7},{%8,%9},{%0,%1,%2,%3};"
                        : "+f"(acc[mt][nt][0]), "+f"(acc[mt][nt][1]),
                          "+f"(acc[mt][nt][2]), "+f"(acc[mt][nt][3])
                        : "r"(af[mt][0]), "r"(af[mt][1]), "r"(af[mt][2]), "r"(af[mt][3]),
                          "r"(bf[nt][0]), "r"(bf[nt][1]));
                }
        }
        __syncthreads();
    }

    #pragma unroll
    for (int mt = 0; mt < 2; mt++)
        #pragma unroll
        for (int nt = 0; nt < 4; nt++) {
            int r = m0 + rbase + mt * 16 + g;
            int cN = n0 + cbase + nt * 8 + 2 * tig;
            *(float2*)&Yb[(long)r * N + cN]       = make_float2(acc[mt][nt][0], acc[mt][nt][1]);
            *(float2*)&Yb[(long)(r + 8) * N + cN] = make_float2(acc[mt][nt][2], acc[mt][nt][3]);
        }
}

// =====================================================================
// Generic tf32 GEMM (NT): A[m*lda+k], B[n*ldb+k]. For FF / out-proj.
// =====================================================================
__global__ __launch_bounds__(256) void gemm_nt(
        const float* __restrict__ A, long aOuter,
        const float* __restrict__ Bm,
        const float* __restrict__ bias,
        float* __restrict__ Y, long yOuter,
        int K, int lda, int ldb, int ldy, int act) {
    __shared__ float smem[128 * 36 + 64 * 36];
    float* As = smem;
    float* Bs = smem + 128 * 36;

    int z = blockIdx.z;
    const float* Ab = A + (long)z * aOuter;
    const float* Bb = Bm;
    float* Yb = Y + (long)z * yOuter;
    int m0 = blockIdx.x * 128, n0 = blockIdx.y * 64;

    int tid = threadIdx.x;
    int w = tid >> 5, lane = tid & 31;
    int wm = w & 3, wn = w >> 2;
    int g = lane >> 2, tig = lane & 3;
    int rbase = wm * 32, cbase = wn * 32;

    float acc[2][4][4];
    #pragma unroll
    for (int i = 0; i < 2; i++)
        #pragma unroll
        for (int j = 0; j < 4; j++)
            #pragma unroll
            for (int l = 0; l < 4; l++) acc[i][j][l] = 0.f;

    float4 aR[4], bR[2];
    int kk4 = (tid & 7) * 4, mb = tid >> 3;

    auto ldg = [&](int k0) {
        #pragma unroll
        for (int it = 0; it < 4; it++)
            aR[it] = *(const float4*)&Ab[(long)(m0 + mb + it * 32) * lda + k0 + kk4];
        #pragma unroll
        for (int it = 0; it < 2; it++)
            bR[it] = *(const float4*)&Bb[(long)(n0 + mb + it * 32) * ldb + k0 + kk4];
    };
    auto sts = [&]() {
        #pragma unroll
        for (int it = 0; it < 4; it++) {
            float4 v = aR[it];
            v.x = f2tf(v.x); v.y = f2tf(v.y); v.z = f2tf(v.z); v.w = f2tf(v.w);
            *(float4*)&As[(mb + it * 32) * 36 + kk4] = v;
        }
        #pragma unroll
        for (int it = 0; it < 2; it++) {
            float4 v = bR[it];
            v.x = f2tf(v.x); v.y = f2tf(v.y); v.z = f2tf(v.z); v.w = f2tf(v.w);
            *(float4*)&Bs[(mb + it * 32) * 36 + kk4] = v;
        }
    };

    ldg(0);
    for (int k0 = 0; k0 < K; k0 += 32) {
        sts();
        __syncthreads();
        if (k0 + 32 < K) ldg(k0 + 32);

        #pragma unroll
        for (int ks = 0; ks < 4; ks++) {
            int kk = ks * 8 + tig, kk2 = kk + 4;
            uint32_t af[2][4], bf[4][2];
            #pragma unroll
            for (int mt = 0; mt < 2; mt++) {
                int r = rbase + mt * 16 + g;
                af[mt][0] = __float_as_uint(As[r       * 36 + kk]);
                af[mt][1] = __float_as_uint(As[(r + 8) * 36 + kk]);
                af[mt][2] = __float_as_uint(As[r       * 36 + kk2]);
                af[mt][3] = __float_as_uint(As[(r + 8) * 36 + kk2]);
            }
            #pragma unroll
            for (int nt = 0; nt < 4; nt++) {
                int cN = cbase + nt * 8 + g;
                bf[nt][0] = __float_as_uint(Bs[cN * 36 + kk]);
                bf[nt][1] = __float_as_uint(Bs[cN * 36 + kk2]);
            }
            #pragma unroll
            for (int mt = 0; mt < 2; mt++)
                #pragma unroll
                for (int nt = 0; nt < 4; nt++) {
                    asm volatile(
                        "mma.sync.aligned.m16n8k8.row.col.f32.tf32.tf32.f32 "
                        "{%0,%1,%2,%3},{%4,%5,%6,%7},{%8,%9},{%0,%1,%2,%3};"
                        : "+f"(acc[mt][nt][0]), "+f"(acc[mt][nt][1]),
                          "+f"(acc[mt][nt][2]), "+f"(acc[mt][nt][3])
                        : "r"(af[mt][0]), "r"(af[mt][1]), "r"(af[mt][2]), "r"(af[mt][3]),
                          "r"(bf[nt][0]), "r"(bf[nt][1]));
                }
        }
        __syncthreads();
    }

    #pragma unroll
    for (int mt = 0; mt < 2; mt++)
        #pragma unroll
        for (int nt = 0; nt < 4; nt++) {
            int r = m0 + rbase + mt * 16 + g;
            int cN = n0 + cbase + nt * 8 + 2 * tig;
            float b0 = bias ? bias[cN] : 0.f;
            float b1 = bias ? bias[cN + 1] : 0.f;
            float v0 = acc[mt][nt][0] + b0;
            float v1 = acc[mt][nt][1] + b1;
            float v2 = acc[mt][nt][2] + b0;
            float v3 = acc[mt][nt][3] + b1;
            if (act == 1) { v0 = silu_f(v0); v1 = silu_f(v1); v2 = silu_f(v2); v3 = silu_f(v3); }
            *(float2*)&Yb[(long)r * ldy + cN]       = make_float2(v0, v1);
            *(float2*)&Yb[(long)(r + 8) * ldy + cN] = make_float2(v2, v3);
        }
}

// =====================================================================
// Flash attention, std MHA: HD=64, S=1024. q-tile 128, key-chunk 64.
// =====================================================================
#define FLASH_SMEM_FLOATS (8704 + 8704 + 4352 + 256 + 256)
__global__ __launch_bounds__(256, 2) void flash_std(
        const float* __restrict__ Q, const float* __restrict__ K,
        const float* __restrict__ V, float* __restrict__ O) {
    extern __shared__ float sm[];
    float* Qs  = sm;
    float* KPs = sm + 8704;
    float* Vs  = sm + 2 * 8704;
    float* redm = sm + 2 * 8704 + 4352;
    float* redl = redm + 256;

    int bh = blockIdx.z;
    int b = bh >> 3, h = bh & 7;
    const float* Qb = Q + (long)b * SS * CCH + h * 64;
    const float* Kb = K + (long)b * SS * CCH + h * 64;
    const float* Vb = V + (long)b * SS * CCH + h * 64;
    float* Ob = O + (long)b * SS * (2 * CCH) + h * 64;
    int q0 = blockIdx.x * 128;

    int tid = threadIdx.x;
    int w = tid >> 5, lane = tid & 31;
    int wm = w & 3, wn = w >> 2;
    int g = lane >> 2, tig = lane & 3;
    int rbase = wm * 32, cbase = wn * 32;

    #pragma unroll
    for (int f = 0; f < 8; f++) {
        int idx = tid + f * 256;
        int r = idx >> 4, kq = (idx & 15) * 4;
        float4 v4 = *(const float4*)&Qb[(long)(q0 + r) * CCH + kq];
        v4.x = f2tf(v4.x * 0.125f); v4.y = f2tf(v4.y * 0.125f);
        v4.z = f2tf(v4.z * 0.125f); v4.w = f2tf(v4.w * 0.125f);
        *(float4*)&Qs[r * 68 + kq] = v4;
    }

    float accO[2][4][4];
    #pragma unroll
    for (int i = 0; i < 2; i++)
        #pragma unroll
        for (int j = 0; j < 4; j++)
            #pragma unroll
            for (int l = 0; l < 4; l++) accO[i][j][l] = 0.f;
    float mst[4] = { -1e30f, -1e30f, -1e30f, -1e30f };
    float lst[4] = { 0.f, 0.f, 0.f, 0.f };

    for (int j = 0; j < 16; j++) {
        __syncthreads();
        #pragma unroll
        for (int f = 0; f < 4; f++) {
            int idx = tid + f * 256;
            int key = idx >> 4, kq = (idx & 15) * 4;
            long goff = (long)(j * 64 + key) * CCH + kq;
            float4 kv = *(const float4*)&Kb[goff];
            kv.x = f2tf(kv.x); kv.y = f2tf(kv.y); kv.z = f2tf(kv.z); kv.w = f2tf(kv.w);
            *(float4*)&KPs[key * 68 + kq] = kv;
            float4 vv = *(const float4*)&Vb[goff];
            vv.x = f2tf(vv.x); vv.y = f2tf(vv.y); vv.z = f2tf(vv.z); vv.w = f2tf(vv.w);
            *(float4*)&Vs[key * 68 + kq] = vv;
        }
        __syncthreads();

        float acc[2][4][4];
        #pragma unroll
        for (int i = 0; i < 2; i++)
            #pragma unroll
            for (int jj = 0; jj < 4; jj++)
                #pragma unroll
                for (int l = 0; l < 4; l++) acc[i][jj][l] = 0.f;
        #pragma unroll
        for (int ks = 0; ks < 8; ks++) {
            int kk = ks * 8 + tig, kk2 = kk + 4;
            uint32_t af[2][4], bf[4][2];
            #pragma unroll
            for (int mt = 0; mt < 2; mt++) {
                int r = rbase + mt * 16 + g;
                af[mt][0] = __float_as_uint(Qs[r       * 68 + kk]);
                af[mt][1] = __float_as_uint(Qs[(r + 8) * 68 + kk]);
                af[mt][2] = __float_as_uint(Qs[r       * 68 + kk2]);
                af[mt][3] = __float_as_uint(Qs[(r + 8) * 68 + kk2]);
            }
            #pragma unroll
            for (int nt = 0; nt < 4; nt++) {
                int cN = cbase + nt * 8 + g;
                bf[nt][0] = __float_as_uint(KPs[cN * 68 + kk]);
                bf[nt][1] = __float_as_uint(KPs[cN * 68 + kk2]);
            }
            #pragma unroll
            for (int mt = 0; mt < 2; mt++)
                #pragma unroll
                for (int nt = 0; nt < 4; nt++) {
                    asm volatile(
                        "mma.sync.aligned.m16n8k8.row.col.f32.tf32.tf32.f32 "
                        "{%0,%1,%2,%3},{%4,%5,%6,%7},{%8,%9},{%0,%1,%2,%3};"
                        : "+f"(acc[mt][nt][0]), "+f"(acc[mt][nt][1]),
                          "+f"(acc[mt][nt][2]), "+f"(acc[mt][nt][3])
                        : "r"(af[mt][0]), "r"(af[mt][1]), "r"(af[mt][2]), "r"(af[mt][3]),
                          "r"(bf[nt][0]), "r"(bf[nt][1]));
                }
        }

        #pragma unroll
        for (int mt = 0; mt < 2; mt++)
            #pragma unroll
            for (int hh = 0; hh < 2; hh++) {
                float mx = -1e30f;
                #pragma unroll
                for (int nt = 0; nt < 4; nt++) {
                    mx = fmaxf(mx, acc[mt][nt][hh * 2]);
                    mx = fmaxf(mx, acc[mt][nt][hh * 2 + 1]);
                }
                mx = fmaxf(mx, __shfl_xor_sync(0xffffffffu, mx, 1));
                mx = fmaxf(mx, __shfl_xor_sync(0xffffffffu, mx, 2));
                if (tig == 0) redm[wn * 128 + rbase + mt * 16 + hh * 8 + g] = mx;
            }
        __syncthreads();

        #pragma unroll
        for (int mt = 0; mt < 2; mt++)
            #pragma unroll
            for (int hh = 0; hh < 2; hh++) {
                int i = mt * 2 + hh;
                int rloc = rbase + mt * 16 + hh * 8 + g;
                float mch = fmaxf(redm[rloc], redm[128 + rloc]);
                float mnew = fmaxf(mst[i], mch);
                float corr = __expf(mst[i] - mnew);
                mst[i] = mnew;
                float s = 0.f;
                #pragma unroll
                for (int nt = 0; nt < 4; nt++) {
                    float p0 = __expf(acc[mt][nt][hh * 2]     - mnew);
                    float p1 = __expf(acc[mt][nt][hh * 2 + 1] - mnew);
                    s += p0 + p1;
                    int col = cbase + nt * 8 + 2 * tig;
                    *(float2*)&KPs[rloc * 68 + col] = make_float2(f2tf(p0), f2tf(p1));
                    accO[mt][nt][hh * 2]     *= corr;
                    accO[mt][nt][hh * 2 + 1] *= corr;
                }
                s += __shfl_xor_sync(0xffffffffu, s, 1);
                s += __shfl_xor_sync(0xffffffffu, s, 2);
                if (tig == 0) redl[wn * 128 + rloc] = s;
                lst[i] *= corr;
            }
        __syncthreads();
        #pragma unroll
        for (int mt = 0; mt < 2; mt++)
            #pragma unroll
            for (int hh = 0; hh < 2; hh++) {
                int rloc = rbase + mt * 16 + hh * 8 + g;
                lst[mt * 2 + hh] += redl[rloc] + redl[128 + rloc];
            }

        #pragma unroll
        for (int ks = 0; ks < 8; ks++) {
            int kk = ks * 8 + tig, kk2 = kk + 4;
            uint32_t af[2][4], bf[4][2];
            #pragma unroll
            for (int mt = 0; mt < 2; mt++) {
                int r = rbase + mt * 16 + g;
                af[mt][0] = __float_as_uint(KPs[r       * 68 + kk]);
                af[mt][1] = __float_as_uint(KPs[(r + 8) * 68 + kk]);
                af[mt][2] = __float_as_uint(KPs[r       * 68 + kk2]);
                af[mt][3] = __float_as_uint(KPs[(r + 8) * 68 + kk2]);
            }
            #pragma unroll
            for (int nt = 0; nt < 4; nt++) {
                int cN = cbase + nt * 8 + g;
                bf[nt][0] = __float_as_uint(Vs[kk  * 68 + cN]);
                bf[nt][1] = __float_as_uint(Vs[kk2 * 68 + cN]);
            }
            #pragma unroll
            for (int mt = 0; mt < 2; mt++)
                #pragma unroll
                for (int nt = 0; nt < 4; nt++) {
                    asm volatile(
                        "mma.sync.aligned.m16n8k8.row.col.f32.tf32.tf32.f32 "
                        "{%0,%1,%2,%3},{%4,%5,%6,%7},{%8,%9},{%0,%1,%2,%3};"
                        : "+f"(accO[mt][nt][0]), "+f"(accO[mt][nt][1]),
                          "+f"(accO[mt][nt][2]), "+f"(accO[mt][nt][3])
                        : "r"(af[mt][0]), "r"(af[mt][1]), "r"(af[mt][2]), "r"(af[mt][3]),
                          "r"(bf[nt][0]), "r"(bf[nt][1]));
                }
        }
    }

    #pragma unroll
    for (int mt = 0; mt < 2; mt++) {
        float inv0 = 1.0f / lst[mt * 2];
        float inv1 = 1.0f / lst[mt * 2 + 1];
        #pragma unroll
        for (int nt = 0; nt < 4; nt++) {
            int r = q0 + rbase + mt * 16 + g;
            int c = cbase + nt * 8 + 2 * tig;
            *(float2*)&Ob[(long)r * 1024 + c] =
                make_float2(accO[mt][nt][0] * inv0, accO[mt][nt][1] * inv0);
            *(float2*)&Ob[(long)(r + 8) * 1024 + c] =
                make_float2(accO[mt][nt][2] * inv1, accO[mt][nt][3] * inv1);
        }
    }
}

// =====================================================================
// Flash attention, multi-scale: D=256, S=1024, single head.
// q-tile 64, key-chunk 64, D CHUNKED into 4x64 so all smem tiles are
// [64][68] (70KB total) -> 2 CTAs/SM with launch_bounds(256,2).
// 8 warps: wm = w&1 (2 m-halves), wn = w>>1 (4 n-slices).
// z = branch*8 + batch. Output comb[:, :, 512+branch*256 ...] ld=1024.
// =====================================================================
#define FM_SMEM_FLOATS (4 * 64 * 68 + 256 + 256)
__global__ __launch_bounds__(256, 2) void flash_multi(
        const float* __restrict__ Q, const float* __restrict__ K,
        const float* __restrict__ V, float* __restrict__ O) {
    extern __shared__ float sm[];
    float* Qs = sm;                    // [64][68] (per d-chunk)
    float* Ks = Qs + 64 * 68;          // [64][68] (per d-chunk) / Vs in PV
    float* Ps = Ks + 64 * 68;          // [64][68]
    float* Vs = Ps + 64 * 68;          // [64][68]
    float* redm = Vs + 64 * 68;        // [4][64]
    float* redl = redm + 256;          // [4][64]

    int z = blockIdx.z;
    const float* Qb = Q + (long)z * SS * C2;
    const float* Kb = K + (long)z * SS * C2;
    const float* Vb = V + (long)z * SS * C2;
    int br = z >> 3, b = z & 7;
    float* Ob = O + (long)b * SS * 1024 + 512 + br * 256;
    int q0 = blockIdx.x * 64;

    int tid = threadIdx.x;
    int w = tid >> 5, lane = tid & 31;
    int wm = w & 1, wn = w >> 1;       // 2m x 4n
    int g = lane >> 2, tig = lane & 3;
    int rbase = wm * 32;

    int st_r = tid >> 4, st_c = (tid & 15) * 4;   // staging: 256 thr cover 64x64 in 4 passes

    float accO[2][8][4];
    #pragma unroll
    for (int i = 0; i < 2; i++)
        #pragma unroll
        for (int j = 0; j < 8; j++)
            #pragma unroll
            for (int l = 0; l < 4; l++) accO[i][j][l] = 0.f;
    float mst[4] = { -1e30f, -1e30f, -1e30f, -1e30f };
    float lst[4] = { 0.f, 0.f, 0.f, 0.f };

    for (int j = 0; j < 16; j++) {
        // ---- scores: acc over D in 4 chunks of 64 ----
        float acc[2][2][4];
        #pragma unroll
        for (int i = 0; i < 2; i++)
            #pragma unroll
            for (int jj = 0; jj < 2; jj++)
                #pragma unroll
                for (int l = 0; l < 4; l++) acc[i][jj][l] = 0.f;

        for (int dc = 0; dc < 4; dc++) {
            __syncthreads();
            #pragma unroll
            for (int f = 0; f < 4; f++) {
                int r = st_r + f * 16;
                float4 qv = *(const float4*)&Qb[(long)(q0 + r) * C2 + dc * 64 + st_c];
                qv.x = f2tf(qv.x * 0.0625f); qv.y = f2tf(qv.y * 0.0625f);
                qv.z = f2tf(qv.z * 0.0625f); qv.w = f2tf(qv.w * 0.0625f);
                *(float4*)&Qs[r * 68 + st_c] = qv;
                float4 kv = *(const float4*)&Kb[(long)(j * 64 + r) * C2 + dc * 64 + st_c];
                kv.x = f2tf(kv.x); kv.y = f2tf(kv.y); kv.z = f2tf(kv.z); kv.w = f2tf(kv.w);
                *(float4*)&Ks[r * 68 + st_c] = kv;
            }
            __syncthreads();
            #pragma unroll
            for (int ks = 0; ks < 8; ks++) {
                int kk = ks * 8 + tig, kk2 = kk + 4;
                uint32_t af[2][4], bf[2][2];
                #pragma unroll
                for (int mt = 0; mt < 2; mt++) {
                    int r = rbase + mt * 16 + g;
                    af[mt][0] = __float_as_uint(Qs[r       * 68 + kk]);
                    af[mt][1] = __float_as_uint(Qs[(r + 8) * 68 + kk]);
                    af[mt][2] = __float_as_uint(Qs[r       * 68 + kk2]);
                    af[mt][3] = __float_as_uint(Qs[(r + 8) * 68 + kk2]);
                }
                #pragma unroll
                for (int nt = 0; nt < 2; nt++) {
                    int cN = wn * 16 + nt * 8 + g;
                    bf[nt][0] = __float_as_uint(Ks[cN * 68 + kk]);
                    bf[nt][1] = __float_as_uint(Ks[cN * 68 + kk2]);
                }
                #pragma unroll
                for (int mt = 0; mt < 2; mt++)
                    #pragma unroll
                    for (int nt = 0; nt < 2; nt++) {
                        asm volatile(
                            "mma.sync.aligned.m16n8k8.row.col.f32.tf32.tf32.f32 "
                            "{%0,%1,%2,%3},{%4,%5,%6,%7},{%8,%9},{%0,%1,%2,%3};"
                            : "+f"(acc[mt][nt][0]), "+f"(acc[mt][nt][1]),
                              "+f"(acc[mt][nt][2]), "+f"(acc[mt][nt][3])
                            : "r"(af[mt][0]), "r"(af[mt][1]), "r"(af[mt][2]), "r"(af[mt][3]),
                              "r"(bf[nt][0]), "r"(bf[nt][1]));
                    }
            }
        }

        // ---- online softmax (4-warp column split) ----
        #pragma unroll
        for (int mt = 0; mt < 2; mt++)
            #pragma unroll
            for (int hh = 0; hh < 2; hh++) {
                float mx = -1e30f;
                #pragma unroll
                for (int nt = 0; nt < 2; nt++) {
                    mx = fmaxf(mx, acc[mt][nt][hh * 2]);
                    mx = fmaxf(mx, acc[mt][nt][hh * 2 + 1]);
                }
                mx = fmaxf(mx, __shfl_xor_sync(0xffffffffu, mx, 1));
                mx = fmaxf(mx, __shfl_xor_sync(0xffffffffu, mx, 2));
                if (tig == 0) redm[wn * 64 + rbase + mt * 16 + hh * 8 + g] = mx;
            }
        __syncthreads();

        #pragma unroll
        for (int mt = 0; mt < 2; mt++)
            #pragma unroll
            for (int hh = 0; hh < 2; hh++) {
                int i = mt * 2 + hh;
                int rloc = rbase + mt * 16 + hh * 8 + g;
                float mch = fmaxf(fmaxf(redm[rloc], redm[64 + rloc]),
                                  fmaxf(redm[128 + rloc], redm[192 + rloc]));
                float mnew = fmaxf(mst[i], mch);
                float corr = __expf(mst[i] - mnew);
                mst[i] = mnew;
                float s = 0.f;
                #pragma unroll
                for (int nt = 0; nt < 2; nt++) {
                    float p0 = __expf(acc[mt][nt][hh * 2]     - mnew);
                    float p1 = __expf(acc[mt][nt][hh * 2 + 1] - mnew);
                    s += p0 + p1;
                    int col = wn * 16 + nt * 8 + 2 * tig;
                    *(float2*)&Ps[rloc * 68 + col] = make_float2(f2tf(p0), f2tf(p1));
                }
                s += __shfl_xor_sync(0xffffffffu, s, 1);
                s += __shfl_xor_sync(0xffffffffu, s, 2);
                if (tig == 0) redl[wn * 64 + rloc] = s;
                lst[i] *= corr;
                #pragma unroll
                for (int nt = 0; nt < 8; nt++) {
                    accO[mt][nt][hh * 2]     *= corr;
                    accO[mt][nt][hh * 2 + 1] *= corr;
                }
            }
        __syncthreads();
        #pragma unroll
        for (int mt = 0; mt < 2; mt++)
            #pragma unroll
            for (int hh = 0; hh < 2; hh++) {
                int rloc = rbase + mt * 16 + hh * 8 + g;
                lst[mt * 2 + hh] += redl[rloc] + redl[64 + rloc]
                                  + redl[128 + rloc] + redl[192 + rloc];
            }

        // ---- O += P V, D in 4 chunks of 64 ----
        for (int dc = 0; dc < 4; dc++) {
            __syncthreads();
            #pragma unroll
            for (int f = 0; f < 4; f++) {
                int r = st_r + f * 16;
                float4 vv = *(const float4*)&Vb[(long)(j * 64 + r) * C2 + dc * 64 + st_c];
                vv.x = f2tf(vv.x); vv.y = f2tf(vv.y); vv.z = f2tf(vv.z); vv.w = f2tf(vv.w);
                *(float4*)&Vs[r * 68 + st_c] = vv;
            }
            __syncthreads();
            #pragma unroll
            for (int ks = 0; ks < 8; ks++) {
                int kk = ks * 8 + tig, kk2 = kk + 4;
                uint32_t af[2][4], bf[2][2];
                #pragma unroll
                for (int mt = 0; mt < 2; mt++) {
                    int r = rbase + mt * 16 + g;
                    af[mt][0] = __float_as_uint(Ps[r       * 68 + kk]);
                    af[mt][1] = __float_as_uint(Ps[(r + 8) * 68 + kk]);
                    af[mt][2] = __float_as_uint(Ps[r       * 68 + kk2]);
                    af[mt][3] = __float_as_uint(Ps[(r + 8) * 68 + kk2]);
                }
                #pragma unroll
                for (int nt = 0; nt < 2; nt++) {
                    int cN = wn * 16 + nt * 8 + g;
                    bf[nt][0] = __float_as_uint(Vs[kk  * 68 + cN]);
                    bf[nt][1] = __float_as_uint(Vs[kk2 * 68 + cN]);
                }
                #pragma unroll
                for (int mt = 0; mt < 2; mt++)
                    #pragma unroll
                    for (int nt = 0; nt < 2; nt++) {
                        asm volatile(
                            "mma.sync.aligned.m16n8k8.row.col.f32.tf32.tf32.f32 "
                            "{%0,%1,%2,%3},{%4,%5,%6,%7},{%8,%9},{%0,%1,%2,%3};"
                            : "+f"(accO[mt][dc * 2 + nt][0]), "+f"(accO[mt][dc * 2 + nt][1]),
                              "+f"(accO[mt][dc * 2 + nt][2]), "+f"(accO[mt][dc * 2 + nt][3])
                            : "r"(af[mt][0]), "r"(af[mt][1]), "r"(af[mt][2]), "r"(af[mt][3]),
                              "r"(bf[nt][0]), "r"(bf[nt][1]));
                    }
            }
        }
    }

    // ---- epilogue ----
    #pragma unroll
    for (int mt = 0; mt < 2; mt++) {
        float inv0 = 1.0f / lst[mt * 2];
        float inv1 = 1.0f / lst[mt * 2 + 1];
        #pragma unroll
        for (int u = 0; u < 8; u++) {
            int dc = u >> 1, nt = u & 1;
            int r = q0 + rbase + mt * 16 + g;
            int c = dc * 64 + wn * 16 + nt * 8 + 2 * tig;
            *(float2*)&Ob[(long)r * 1024 + c] =
                make_float2(accO[mt][u][0] * inv0, accO[mt][u][1] * inv0);
            *(float2*)&Ob[(long)(r + 8) * 1024 + c] =
                make_float2(accO[mt][u][2] * inv1, accO[mt][u][3] * inv1);
        }
    }
}

// ---------------- conv 1x1 (512 -> 64) + SiLU ----------------
__global__ void conv1_silu(const float* __restrict__ x, const float* __restrict__ w,
                           const float* __restrict__ bias, float* __restrict__ y) {
    __shared__ float ws[8 * 512];
    int tid = threadIdx.x;
    int o0 = blockIdx.y * 8, b = blockIdx.z;
    for (int i = tid; i < 8 * 512; i += 256) ws[i] = w[(long)o0 * 512 + i];
    __syncthreads();
    int s = blockIdx.x * 256 + tid;
    float acc[8];
    #pragma unroll
    for (int oo = 0; oo < 8; oo++) acc[oo] = bias[o0 + oo];
    const float* xb = x + (long)b * CCH * SS + s;
    for (int c = 0; c < 512; c++) {
        float xv = xb[(long)c * SS];
        #pragma unroll
        for (int oo = 0; oo < 8; oo++) acc[oo] += xv * ws[oo * 512 + c];
    }
    #pragma unroll
    for (int oo = 0; oo < 8; oo++)
        y[(long)b * C8 * SS + (long)(o0 + oo) * SS + s] = silu_f(acc[oo]);
}

// ---------------- conv 3x3 (64 -> 64, SAME) + SiLU ----------------
__global__ void conv2_silu(const float* __restrict__ x, const float* __restrict__ w,
                           const float* __restrict__ bias, float* __restrict__ y) {
    __shared__ float ws[8 * 576];
    int tid = threadIdx.x;
    int o0 = blockIdx.y * 8, b = blockIdx.z;
    for (int i = tid; i < 8 * 576; i += 256) ws[i] = w[(long)o0 * 576 + i];
    __syncthreads();
    int s = blockIdx.x * 256 + tid;
    int yy = s >> 5, xx = s & 31;
    float acc[8];
    #pragma unroll
    for (int oo = 0; oo < 8; oo++) acc[oo] = bias[o0 + oo];
    const float* xb = x + (long)b * C8 * SS;
    for (int ci = 0; ci < 64; ci++) {
        #pragma unroll
        for (int ky = 0; ky < 3; ky++) {
            int py = yy + ky - 1;
            if (py < 0 || py >= 32) continue;
            #pragma unroll
            for (int kx = 0; kx < 3; kx++) {
                int px = xx + kx - 1;
                if (px < 0 || px >= 32) continue;
                float av = xb[(long)ci * SS + py * 32 + px];
                #pragma unroll
                for (int oo = 0; oo < 8; oo++)
                    acc[oo] += av * ws[oo * 576 + ci * 9 + ky * 3 + kx];
            }
        }
    }
    #pragma unroll
    for (int oo = 0; oo < 8; oo++)
        y[(long)b * C8 * SS + (long)(o0 + oo) * SS + s] = silu_f(acc[oo]);
}

// ---------------- conv 1x1 (64 -> 1) + sigmoid ----------------
__global__ void conv3_sig(const float* __restrict__ x, const float* __restrict__ w,
                          const float* __restrict__ bias, float* __restrict__ y) {
    int idx = blockIdx.x * 256 + threadIdx.x;
    int b = idx >> 10, s = idx & 1023;
    float acc = bias[0];
    const float* xb = x + (long)b * C8 * SS + s;
    #pragma unroll 8
    for (int i = 0; i < 64; i++) acc += xb[(long)i * SS] * w[i];
    y[idx] = 1.0f / (1.0f + expf(-acc));
}

// ---------------- spatial_enhanced = hs * sw ----------------
__global__ void senh_mul(const float* __restrict__ hs, const float* __restrict__ sw,
                         float* __restrict__ y) {
    long idx = (long)blockIdx.x * 256 + threadIdx.x;
    int b = (int)(idx >> 19);
    int s = (int)(idx & 1023);
    y[idx] = hs[idx] * sw[b * 1024 + s];
}

// ---------------- launch ----------------
static float* sym(const void* s) { void* p = nullptr; cudaGetSymbolAddress(&p, s); return (float*)p; }

extern "C" void kernel_launch(void* const* d_in, const int* in_sizes, int n_in,
                              void* d_out, int out_size) {
    (void)in_sizes; (void)n_in; (void)out_size;
    const float* x      = (const float*)d_in[0];
    const float* pre_g  = (const float*)d_in[1];
    const float* pre_b  = (const float*)d_in[2];
    const float* norm_g = (const float*)d_in[3];
    const float* norm_b = (const float*)d_in[4];
    const float* post_g = (const float*)d_in[5];
    const float* post_b = (const float*)d_in[6];
    const float* pos    = (const float*)d_in[7];
    const float* sa_w1  = (const float*)d_in[8];
    const float* sa_b1  = (const float*)d_in[9];
    const float* sa_w2  = (const float*)d_in[10];
    const float* sa_b2  = (const float*)d_in[11];
    const float* sa_w3  = (const float*)d_in[12];
    const float* sa_b3  = (const float*)d_in[13];
    const float* wq     = (const float*)d_in[14];
    const float* wk     = (const float*)d_in[15];
    const float* wv     = (const float*)d_in[16];
    const float* wq0    = (const float*)d_in[17];
    const float* wk0    = (const float*)d_in[18];
    const float* wv0    = (const float*)d_in[19];
    const float* wq1    = (const float*)d_in[20];
    const float* wk1    = (const float*)d_in[21];
    const float* wv1    = (const float*)d_in[22];
    const float* ff_w1  = (const float*)d_in[23];
    const float* ff_b1  = (const float*)d_in[24];
    const float* ff_w2  = (const float*)d_in[25];
    const float* ff_b2  = (const float*)d_in[26];
    const float* out_w  = (const float*)d_in[27];
    const float* out_b  = (const float*)d_in[28];
    float* out = (float*)d_out;

    float *hs = sym(d_hs), *shn = sym(d_shn), *senh = sym(d_senh);
    float *a1 = sym(d_a1), *a2 = sym(d_a2), *sw = sym(d_swt);
    float *q = sym(d_q), *k = sym(d_k), *v = sym(d_v);
    float *qm = sym(d_qm), *km = sym(d_km), *vm = sym(d_vm);
    float *comb = sym(d_comb), *f1 = sym(d_f1), *fus = sym(d_fus), *fin = sym(d_fin);

    const int fsSmem = FLASH_SMEM_FLOATS * 4;
    const int fmSmem = FM_SMEM_FLOATS * 4;
    cudaFuncSetAttribute(flash_std, cudaFuncAttributeMaxDynamicSharedMemorySize, fsSmem);
    cudaFuncSetAttribute(flash_multi, cudaFuncAttributeMaxDynamicSharedMemorySize, fmSmem);

    gn_cmajor<<<BATCH * NGR, 256>>>(x, pre_g, pre_b, pos, hs);
    conv1_silu<<<dim3(4, 8, BATCH), 256>>>(hs, sa_w1, sa_b1, a1);
    conv2_silu<<<dim3(4, 8, BATCH), 256>>>(a1, sa_w2, sa_b2, a2);
    conv3_sig<<<BATCH * SS / 256, 256>>>(a2, sa_w3, sa_b3, sw);
    senh_mul<<<BATCH * CCH * SS / 256, 256>>>(hs, sw, senh);
    gn_cmajor<<<BATCH * NGR, 256>>>(hs, norm_g, norm_b, nullptr, shn);

    // QKV projections (one launch)
    Ptr6 pq = {};
    pq.A[0] = shn; pq.A[1] = shn; pq.A[2] = shn;
    pq.W[0] = wq;  pq.W[1] = wk;  pq.W[2] = wv;
    pq.Y[0] = q;   pq.Y[1] = k;   pq.Y[2] = v;
    gemm_proj<<<dim3(8, 8, 24), 256>>>(pq, 512);

    // multi-scale projections (one launch)
    long moff = 8LL * SS * C2;
    Ptr6 pm = {};
    pm.A[0] = senh; pm.A[1] = shn; pm.A[2] = shn;
    pm.A[3] = senh; pm.A[4] = shn; pm.A[5] = shn;
    pm.W[0] = wq0;  pm.W[1] = wk0; pm.W[2] = wv0;
    pm.W[3] = wq1;  pm.W[4] = wk1; pm.W[5] = wv1;
    pm.Y[0] = qm;        pm.Y[1] = km;        pm.Y[2] = vm;
    pm.Y[3] = qm + moff; pm.Y[4] = km + moff; pm.Y[5] = vm + moff;
    gemm_proj<<<dim3(8, 4, 48), 256>>>(pm, 256);

    // std MHA flash -> comb[:, :, 0:512]
    flash_std<<<dim3(8, 1, BATCH * NHD), 256, fsSmem>>>(q, k, v, comb);
    // multi-scale flash -> comb[:, :, 512:1024]
    flash_multi<<<dim3(16, 1, 16), 256, fmSmem>>>(qm, km, vm, comb);

    // ff1 (silu)
    gemm_nt<<<dim3(8, 8, BATCH), 256>>>(comb, (long)SS * 2 * CCH, ff_w1, ff_b1,
                                        f1, (long)SS * CCH, 2 * CCH, 2 * CCH, 2 * CCH, CCH, 1);
    // ff2
    gemm_nt<<<dim3(8, 8, BATCH), 256>>>(f1, (long)SS * CCH, ff_w2, ff_b2,
                                        fus, (long)SS * CCH, CCH, CCH, CCH, CCH, 0);
    // out proj
    gemm_nt<<<dim3(8, 8, BATCH), 256>>>(fus, (long)SS * CCH, out_w, out_b,
                                        fin, (long)SS * CCH, CCH, CCH, CCH, CCH, 0);
    // post GN + residual
    gn_post_k<<<BATCH * NGR, 256>>>(fin, post_g, post_b, x, out);
}

// round 6
// speedup vs baseline: 1.3114x; 1.3114x over previous
#include <cuda_runtime.h>
#include <cuda_fp16.h>
#include <math.h>
#include <stdint.h>

#define BATCH 8
#define CCH 512
#define SS 1024
#define NHD 8
#define NGR 32
#define CG 16
#define C8 64
#define C2 256
#define GEPS 1e-6f

// ---------------- static scratch ----------------
__device__ float d_hs   [BATCH*CCH*SS];
__device__ float d_shn  [BATCH*CCH*SS];
__device__ float d_senh [BATCH*CCH*SS];
__device__ float d_a1   [BATCH*C8*SS];
__device__ float d_a2   [BATCH*C8*SS];
__device__ float d_swt  [BATCH*SS];
__device__ float d_q    [BATCH*SS*CCH];
__device__ float d_k    [BATCH*SS*CCH];
__device__ float d_v    [BATCH*SS*CCH];
__device__ float d_qm   [2*BATCH*SS*C2];
__device__ float d_km   [2*BATCH*SS*C2];
__device__ float d_vm   [2*BATCH*SS*C2];
__device__ float d_comb [BATCH*SS*2*CCH];
__device__ float d_f1   [BATCH*SS*CCH];
__device__ float d_fus  [BATCH*SS*CCH];
__device__ float d_fin  [BATCH*SS*CCH];

// ---------------- helpers ----------------
__device__ __forceinline__ float blk_sum(float v, float* sb, int tid) {
    sb[tid] = v; __syncthreads();
    for (int o = 128; o > 0; o >>= 1) { if (tid < o) sb[tid] += sb[tid + o]; __syncthreads(); }
    float r = sb[0]; __syncthreads(); return r;
}
__device__ __forceinline__ float silu_f(float x) { return x / (1.0f + expf(-x)); }
__device__ __forceinline__ uint32_t pack2(float a, float b) {
    __half2 h = __floats2half2_rn(a, b);
    return *reinterpret_cast<uint32_t*>(&h);
}

#define MMA16(d, a0, a1, a2, a3, b0, b1) \
    asm volatile("mma.sync.aligned.m16n8k16.row.col.f32.f16.f16.f32 " \
        "{%0,%1,%2,%3},{%4,%5,%6,%7},{%8,%9},{%0,%1,%2,%3};" \
        : "+f"((d)[0]), "+f"((d)[1]), "+f"((d)[2]), "+f"((d)[3]) \
        : "r"(a0), "r"(a1), "r"(a2), "r"(a3), "r"(b0), "r"(b1))

// ---------------- group norm, channel-major, optional pos add ----------------
__global__ void gn_cmajor(const float* __restrict__ x, const float* __restrict__ g,
                          const float* __restrict__ be, const float* __restrict__ pos,
                          float* __restrict__ y) {
    __shared__ float sb[256];
    int tid = threadIdx.x;
    int b = blockIdx.x / NGR, gi = blockIdx.x % NGR;
    long base = (long)b * CCH * SS + (long)gi * CG * SS;
    float s1 = 0.f, s2 = 0.f;
    for (int i = tid; i < CG * SS; i += 256) { float v = x[base + i]; s1 += v; s2 += v * v; }
    s1 = blk_sum(s1, sb, tid);
    s2 = blk_sum(s2, sb, tid);
    float mu = s1 / (float)(CG * SS);
    float var = s2 / (float)(CG * SS) - mu * mu;
    float inv = rsqrtf(var + GEPS);
    for (int i = tid; i < CG * SS; i += 256) {
        int cl = i >> 10, s = i & 1023;
        int c = gi * CG + cl;
        float v = (x[base + i] - mu) * inv * g[c] + be[c];
        if (pos) v += pos[(long)c * SS + s];
        y[base + i] = v;
    }
}

// ---------------- group norm token-major + residual, out (B,C,S) ----------------
__global__ void gn_post_k(const float* __restrict__ xt, const float* __restrict__ g,
                          const float* __restrict__ be, const float* __restrict__ resid,
                          float* __restrict__ y) {
    __shared__ float sb[256];
    int tid = threadIdx.x;
    int b = blockIdx.x / NGR, gi = blockIdx.x % NGR;
    long tbase = (long)b * SS * CCH + gi * CG;
    float s1 = 0.f, s2 = 0.f;
    for (int i = tid; i < CG * SS; i += 256) {
        int s = i >> 4, cl = i & 15;
        float v = xt[tbase + (long)s * CCH + cl]; s1 += v; s2 += v * v;
    }
    s1 = blk_sum(s1, sb, tid);
    s2 = blk_sum(s2, sb, tid);
    float mu = s1 / (float)(CG * SS);
    float var = s2 / (float)(CG * SS) - mu * mu;
    float inv = rsqrtf(var + GEPS);
    for (int i = tid; i < CG * SS; i += 256) {
        int s = i >> 4, cl = i & 15;
        int c = gi * CG + cl;
        float v = (xt[tbase + (long)s * CCH + cl] - mu) * inv * g[c] + be[c];
        long oidx = (long)b * CCH * SS + (long)c * SS + s;
        y[oidx] = v + resid[oidx];
    }
}

// =====================================================================
// fp16 projection GEMM (TN): A (C,S) channel-major, W (N,512) row-major.
// Block 128x64, BK=32, 256 thr. A staged m-major half2 with XOR swizzle.
// =====================================================================
struct Ptr6 { const float* A[6]; const float* W[6]; float* Y[6]; };

__global__ __launch_bounds__(256) void gemm_proj(Ptr6 ps, int N) {
    __shared__ uint32_t As32[128 * 20];
    __shared__ uint32_t Bs32[64 * 20];

    int z = blockIdx.z;
    int which = z >> 3, b = z & 7;
    const float* Ab = ps.A[which] + (long)b * CCH * SS;
    const float* Bb = ps.W[which];
    float*       Yb = ps.Y[which] + (long)b * SS * N;
    int m0 = blockIdx.x * 128, n0 = blockIdx.y * 64;

    int tid = threadIdx.x;
    int w = tid >> 5, lane = tid & 31;
    int wm = w & 3, wn = w >> 2;
    int g = lane >> 2, tig = lane & 3;
    int rbase = wm * 32, cbase = wn * 32;

    float acc[2][4][4];
    #pragma unroll
    for (int i = 0; i < 2; i++)
        #pragma unroll
        for (int j = 0; j < 4; j++)
            #pragma unroll
            for (int l = 0; l < 4; l++) acc[i][j][l] = 0.f;

    // staging registers
    float2 aR[8];
    float4 bR[2];
    int a_ml = tid & 31, a_kp = tid >> 5;
    int b_k4 = (tid & 7) * 4, b_nb = tid >> 3;

    auto ldg = [&](int k0) {
        #pragma unroll
        for (int it = 0; it < 8; it++) {
            int ml = a_ml + 32 * (it & 3);
            int kpp = a_kp + 8 * (it >> 2);
            long off = (long)(k0 + 2 * kpp) * SS + m0 + ml;
            aR[it].x = Ab[off];
            aR[it].y = Ab[off + SS];
        }
        #pragma unroll
        for (int it = 0; it < 2; it++)
            bR[it] = *(const float4*)&Bb[(long)(n0 + b_nb + it * 32) * 512 + k0 + b_k4];
    };
    auto sts = [&]() {
        #pragma unroll
        for (int it = 0; it < 8; it++) {
            int ml = a_ml + 32 * (it & 3);
            int kpp = a_kp + 8 * (it >> 2);
            As32[ml * 20 + (kpp ^ ((ml >> 3) & 3))] = pack2(aR[it].x, aR[it].y);
        }
        #pragma unroll
        for (int it = 0; it < 2; it++) {
            int n = b_nb + it * 32;
            Bs32[n * 20 + (tid & 7) * 2]     = pack2(bR[it].x, bR[it].y);
            Bs32[n * 20 + (tid & 7) * 2 + 1] = pack2(bR[it].z, bR[it].w);
        }
    };

    ldg(0);
    for (int k0 = 0; k0 < 512; k0 += 32) {
        sts();
        __syncthreads();
        if (k0 + 32 < 512) ldg(k0 + 32);

        #pragma unroll
        for (int ks = 0; ks < 2; ks++) {
            int kw = ks * 8;
            uint32_t af[2][4], bf[4][2];
            #pragma unroll
            for (int mt = 0; mt < 2; mt++) {
                int r = rbase + mt * 16 + g;
                int xr = (r >> 3) & 3, xr8 = ((r + 8) >> 3) & 3;
                int w0 = (kw + tig) ^ xr, w8 = (kw + tig) ^ xr8;
                af[mt][0] = As32[r * 20 + w0];
                af[mt][1] = As32[(r + 8) * 20 + w8];
                af[mt][2] = As32[r * 20 + w0 + 4];
                af[mt][3] = As32[(r + 8) * 20 + w8 + 4];
            }
            #pragma unroll
            for (int nt = 0; nt < 4; nt++) {
                int cN = cbase + nt * 8 + g;
                bf[nt][0] = Bs32[cN * 20 + kw + tig];
                bf[nt][1] = Bs32[cN * 20 + kw + tig + 4];
            }
            #pragma unroll
            for (int mt = 0; mt < 2; mt++)
                #pragma unroll
                for (int nt = 0; nt < 4; nt++)
                    MMA16(acc[mt][nt], af[mt][0], af[mt][1], af[mt][2], af[mt][3],
                          bf[nt][0], bf[nt][1]);
        }
        __syncthreads();
    }

    #pragma unroll
    for (int mt = 0; mt < 2; mt++)
        #pragma unroll
        for (int nt = 0; nt < 4; nt++) {
            int r = m0 + rbase + mt * 16 + g;
            int cN = n0 + cbase + nt * 8 + 2 * tig;
            *(float2*)&Yb[(long)r * N + cN]       = make_float2(acc[mt][nt][0], acc[mt][nt][1]);
            *(float2*)&Yb[(long)(r + 8) * N + cN] = make_float2(acc[mt][nt][2], acc[mt][nt][3]);
        }
}

// =====================================================================
// fp16 GEMM (NT): A[m][k], B[n][k] row-major. For FF / out-proj.
// =====================================================================
__global__ __launch_bounds__(256) void gemm_nt(
        const float* __restrict__ A, long aOuter,
        const float* __restrict__ Bm,
        const float* __restrict__ bias,
        float* __restrict__ Y, long yOuter,
        int K, int lda, int ldb, int ldy, int act) {
    __shared__ uint32_t As32[128 * 20];
    __shared__ uint32_t Bs32[64 * 20];

    int z = blockIdx.z;
    const float* Ab = A + (long)z * aOuter;
    const float* Bb = Bm;
    float* Yb = Y + (long)z * yOuter;
    int m0 = blockIdx.x * 128, n0 = blockIdx.y * 64;

    int tid = threadIdx.x;
    int w = tid >> 5, lane = tid & 31;
    int wm = w & 3, wn = w >> 2;
    int g = lane >> 2, tig = lane & 3;
    int rbase = wm * 32, cbase = wn * 32;

    float acc[2][4][4];
    #pragma unroll
    for (int i = 0; i < 2; i++)
        #pragma unroll
        for (int j = 0; j < 4; j++)
            #pragma unroll
            for (int l = 0; l < 4; l++) acc[i][j][l] = 0.f;

    float4 aR[4], bR[2];
    int k4 = (tid & 7) * 4, mb = tid >> 3;

    auto ldg = [&](int k0) {
        #pragma unroll
        for (int it = 0; it < 4; it++)
            aR[it] = *(const float4*)&Ab[(long)(m0 + mb + it * 32) * lda + k0 + k4];
        #pragma unroll
        for (int it = 0; it < 2; it++)
            bR[it] = *(const float4*)&Bb[(long)(n0 + mb + it * 32) * ldb + k0 + k4];
    };
    auto sts = [&]() {
        int w2 = (tid & 7) * 2;
        #pragma unroll
        for (int it = 0; it < 4; it++) {
            int m = mb + it * 32;
            As32[m * 20 + w2]     = pack2(aR[it].x, aR[it].y);
            As32[m * 20 + w2 + 1] = pack2(aR[it].z, aR[it].w);
        }
        #pragma unroll
        for (int it = 0; it < 2; it++) {
            int n = mb + it * 32;
            Bs32[n * 20 + w2]     = pack2(bR[it].x, bR[it].y);
            Bs32[n * 20 + w2 + 1] = pack2(bR[it].z, bR[it].w);
        }
    };

    ldg(0);
    for (int k0 = 0; k0 < K; k0 += 32) {
        sts();
        __syncthreads();
        if (k0 + 32 < K) ldg(k0 + 32);

        #pragma unroll
        for (int ks = 0; ks < 2; ks++) {
            int kw = ks * 8;
            uint32_t af[2][4], bf[4][2];
            #pragma unroll
            for (int mt = 0; mt < 2; mt++) {
                int r = rbase + mt * 16 + g;
                af[mt][0] = As32[r * 20 + kw + tig];
                af[mt][1] = As32[(r + 8) * 20 + kw + tig];
                af[mt][2] = As32[r * 20 + kw + tig + 4];
                af[mt][3] = As32[(r + 8) * 20 + kw + tig + 4];
            }
            #pragma unroll
            for (int nt = 0; nt < 4; nt++) {
                int cN = cbase + nt * 8 + g;
                bf[nt][0] = Bs32[cN * 20 + kw + tig];
                bf[nt][1] = Bs32[cN * 20 + kw + tig + 4];
            }
            #pragma unroll
            for (int mt = 0; mt < 2; mt++)
                #pragma unroll
                for (int nt = 0; nt < 4; nt++)
                    MMA16(acc[mt][nt], af[mt][0], af[mt][1], af[mt][2], af[mt][3],
                          bf[nt][0], bf[nt][1]);
        }
        __syncthreads();
    }

    #pragma unroll
    for (int mt = 0; mt < 2; mt++)
        #pragma unroll
        for (int nt = 0; nt < 4; nt++) {
            int r = m0 + rbase + mt * 16 + g;
            int cN = n0 + cbase + nt * 8 + 2 * tig;
            float b0 = bias ? bias[cN] : 0.f;
            float b1 = bias ? bias[cN + 1] : 0.f;
            float v0 = acc[mt][nt][0] + b0;
            float v1 = acc[mt][nt][1] + b1;
            float v2 = acc[mt][nt][2] + b0;
            float v3 = acc[mt][nt][3] + b1;
            if (act == 1) { v0 = silu_f(v0); v1 = silu_f(v1); v2 = silu_f(v2); v3 = silu_f(v3); }
            *(float2*)&Yb[(long)r * ldy + cN]       = make_float2(v0, v1);
            *(float2*)&Yb[(long)(r + 8) * ldy + cN] = make_float2(v2, v3);
        }
}

// =====================================================================
// fp16 flash attention, std MHA: HD=64, S=1024. q-tile 128, key-chunk 64.
// Qs [128][36w], KP [128][36w] (K rows 0-63, P all), VT [64hd][36w] XOR.
// =====================================================================
#define FS_WORDS (128 * 36 + 128 * 36 + 64 * 36 + 512)
__global__ __launch_bounds__(256, 2) void flash_std(
        const float* __restrict__ Q, const float* __restrict__ K,
        const float* __restrict__ V, float* __restrict__ O) {
    extern __shared__ uint32_t smw[];
    uint32_t* Qs = smw;
    uint32_t* KP = smw + 128 * 36;
    uint32_t* VT = smw + 2 * 128 * 36;
    float* redm = (float*)(smw + 2 * 128 * 36 + 64 * 36);
    float* redl = redm + 256;

    int bh = blockIdx.z;
    int b = bh >> 3, h = bh & 7;
    const float* Qb = Q + (long)b * SS * CCH + h * 64;
    const float* Kb = K + (long)b * SS * CCH + h * 64;
    const float* Vb = V + (long)b * SS * CCH + h * 64;
    float* Ob = O + (long)b * SS * (2 * CCH) + h * 64;
    int q0 = blockIdx.x * 128;

    int tid = threadIdx.x;
    int w = tid >> 5, lane = tid & 31;
    int wm = w & 3, wn = w >> 2;
    int g = lane >> 2, tig = lane & 3;
    int rbase = wm * 32, cbase = wn * 32;

    // stage Q (scaled by 0.125)
    #pragma unroll
    for (int f = 0; f < 8; f++) {
        int idx = tid + f * 256;
        int r = idx >> 4, c2 = (idx & 15) * 2;
        float4 v4 = *(const float4*)&Qb[(long)(q0 + r) * CCH + (idx & 15) * 4];
        Qs[r * 36 + c2]     = pack2(v4.x * 0.125f, v4.y * 0.125f);
        Qs[r * 36 + c2 + 1] = pack2(v4.z * 0.125f, v4.w * 0.125f);
    }

    float accO[2][4][4];
    #pragma unroll
    for (int i = 0; i < 2; i++)
        #pragma unroll
        for (int j = 0; j < 4; j++)
            #pragma unroll
            for (int l = 0; l < 4; l++) accO[i][j][l] = 0.f;
    float mst[4] = { -1e30f, -1e30f, -1e30f, -1e30f };
    float lst[4] = { 0.f, 0.f, 0.f, 0.f };

    int v_hd = tid & 63, v_kp = tid >> 6;
    int v_x = (v_hd >> 3) & 3;

    for (int j = 0; j < 16; j++) {
        __syncthreads();
        // stage K (n-major) and V transposed
        #pragma unroll
        for (int f = 0; f < 4; f++) {
            int idx = tid + f * 256;
            int r = idx >> 4, c2 = (idx & 15) * 2;
            float4 kv = *(const float4*)&Kb[(long)(j * 64 + r) * CCH + (idx & 15) * 4];
            KP[r * 36 + c2]     = pack2(kv.x, kv.y);
            KP[r * 36 + c2 + 1] = pack2(kv.z, kv.w);
        }
        #pragma unroll
        for (int it = 0; it < 8; it++) {
            int keyp = v_kp + 4 * it;
            long o0 = (long)(j * 64 + 2 * keyp) * CCH + v_hd;
            float f0 = Vb[o0], f1 = Vb[o0 + CCH];
            VT[v_hd * 36 + (keyp ^ v_x)] = pack2(f0, f1);
        }
        __syncthreads();

        // scores S = Q K^T
        float acc[2][4][4];
        #pragma unroll
        for (int i = 0; i < 2; i++)
            #pragma unroll
            for (int jj = 0; jj < 4; jj++)
                #pragma unroll
                for (int l = 0; l < 4; l++) acc[i][jj][l] = 0.f;
        #pragma unroll
        for (int ks = 0; ks < 4; ks++) {
            int kw = ks * 8;
            uint32_t af[2][4], bf[4][2];
            #pragma unroll
            for (int mt = 0; mt < 2; mt++) {
                int r = rbase + mt * 16 + g;
                af[mt][0] = Qs[r * 36 + kw + tig];
                af[mt][1] = Qs[(r + 8) * 36 + kw + tig];
                af[mt][2] = Qs[r * 36 + kw + tig + 4];
                af[mt][3] = Qs[(r + 8) * 36 + kw + tig + 4];
            }
            #pragma unroll
            for (int nt = 0; nt < 4; nt++) {
                int cN = cbase + nt * 8 + g;
                bf[nt][0] = KP[cN * 36 + kw + tig];
                bf[nt][1] = KP[cN * 36 + kw + tig + 4];
            }
            #pragma unroll
            for (int mt = 0; mt < 2; mt++)
                #pragma unroll
                for (int nt = 0; nt < 4; nt++)
                    MMA16(acc[mt][nt], af[mt][0], af[mt][1], af[mt][2], af[mt][3],
                          bf[nt][0], bf[nt][1]);
        }

        // row max
        #pragma unroll
        for (int mt = 0; mt < 2; mt++)
            #pragma unroll
            for (int hh = 0; hh < 2; hh++) {
                float mx = -1e30f;
                #pragma unroll
                for (int nt = 0; nt < 4; nt++) {
                    mx = fmaxf(mx, acc[mt][nt][hh * 2]);
                    mx = fmaxf(mx, acc[mt][nt][hh * 2 + 1]);
                }
                mx = fmaxf(mx, __shfl_xor_sync(0xffffffffu, mx, 1));
                mx = fmaxf(mx, __shfl_xor_sync(0xffffffffu, mx, 2));
                if (tig == 0) redm[wn * 128 + rbase + mt * 16 + hh * 8 + g] = mx;
            }
        __syncthreads();

        // exp, write P (half2 into KP), sums, rescale O
        #pragma unroll
        for (int mt = 0; mt < 2; mt++)
            #pragma unroll
            for (int hh = 0; hh < 2; hh++) {
                int i = mt * 2 + hh;
                int rloc = rbase + mt * 16 + hh * 8 + g;
                float mch = fmaxf(redm[rloc], redm[128 + rloc]);
                float mnew = fmaxf(mst[i], mch);
                float corr = __expf(mst[i] - mnew);
                mst[i] = mnew;
                float s = 0.f;
                #pragma unroll
                for (int nt = 0; nt < 4; nt++) {
                    float p0 = __expf(acc[mt][nt][hh * 2]     - mnew);
                    float p1 = __expf(acc[mt][nt][hh * 2 + 1] - mnew);
                    s += p0 + p1;
                    KP[rloc * 36 + wn * 16 + nt * 4 + tig] = pack2(p0, p1);
                    accO[mt][nt][hh * 2]     *= corr;
                    accO[mt][nt][hh * 2 + 1] *= corr;
                }
                s += __shfl_xor_sync(0xffffffffu, s, 1);
                s += __shfl_xor_sync(0xffffffffu, s, 2);
                if (tig == 0) redl[wn * 128 + rloc] = s;
                lst[i] *= corr;
            }
        __syncthreads();
        #pragma unroll
        for (int mt = 0; mt < 2; mt++)
            #pragma unroll
            for (int hh = 0; hh < 2; hh++) {
                int rloc = rbase + mt * 16 + hh * 8 + g;
                lst[mt * 2 + hh] += redl[rloc] + redl[128 + rloc];
            }

        // O += P V
        #pragma unroll
        for (int ks = 0; ks < 4; ks++) {
            int kw = ks * 8;
            uint32_t af[2][4], bf[4][2];
            #pragma unroll
            for (int mt = 0; mt < 2; mt++) {
                int r = rbase + mt * 16 + g;
                af[mt][0] = KP[r * 36 + kw + tig];
                af[mt][1] = KP[(r + 8) * 36 + kw + tig];
                af[mt][2] = KP[r * 36 + kw + tig + 4];
                af[mt][3] = KP[(r + 8) * 36 + kw + tig + 4];
            }
            #pragma unroll
            for (int nt = 0; nt < 4; nt++) {
                int cN = cbase + nt * 8 + g;
                int xc = (cN >> 3) & 3;
                int w0 = (kw + tig) ^ xc;
                bf[nt][0] = VT[cN * 36 + w0];
                bf[nt][1] = VT[cN * 36 + w0 + 4];
            }
            #pragma unroll
            for (int mt = 0; mt < 2; mt++)
                #pragma unroll
                for (int nt = 0; nt < 4; nt++)
                    MMA16(accO[mt][nt], af[mt][0], af[mt][1], af[mt][2], af[mt][3],
                          bf[nt][0], bf[nt][1]);
        }
    }

    #pragma unroll
    for (int mt = 0; mt < 2; mt++) {
        float inv0 = 1.0f / lst[mt * 2];
        float inv1 = 1.0f / lst[mt * 2 + 1];
        #pragma unroll
        for (int nt = 0; nt < 4; nt++) {
            int r = q0 + rbase + mt * 16 + g;
            int c = cbase + nt * 8 + 2 * tig;
            *(float2*)&Ob[(long)r * 1024 + c] =
                make_float2(accO[mt][nt][0] * inv0, accO[mt][nt][1] * inv0);
            *(float2*)&Ob[(long)(r + 8) * 1024 + c] =
                make_float2(accO[mt][nt][2] * inv1, accO[mt][nt][3] * inv1);
        }
    }
}

// =====================================================================
// fp16 flash attention, multi-scale: D=256 chunked 4x64, q-tile 64,
// key-chunk 64. 8 warps (2m x 4n). z = branch*8 + batch.
// =====================================================================
#define FM_WORDS (4 * 64 * 36 + 512)
__global__ __launch_bounds__(256, 2) void flash_multi(
        const float* __restrict__ Q, const float* __restrict__ K,
        const float* __restrict__ V, float* __restrict__ O) {
    extern __shared__ uint32_t smw[];
    uint32_t* Qs = smw;                 // [64][36]
    uint32_t* Ks = smw + 64 * 36;       // [64][36]
    uint32_t* Ps = smw + 2 * 64 * 36;   // [64][36]
    uint32_t* VT = smw + 3 * 64 * 36;   // [64 hd][36] transposed, XOR
    float* redm = (float*)(smw + 4 * 64 * 36);
    float* redl = redm + 256;

    int z = blockIdx.z;
    const float* Qb = Q + (long)z * SS * C2;
    const float* Kb = K + (long)z * SS * C2;
    const float* Vb = V + (long)z * SS * C2;
    int br = z >> 3, b = z & 7;
    float* Ob = O + (long)b * SS * 1024 + 512 + br * 256;
    int q0 = blockIdx.x * 64;

    int tid = threadIdx.x;
    int w = tid >> 5, lane = tid & 31;
    int wm = w & 1, wn = w >> 1;
    int g = lane >> 2, tig = lane & 3;
    int rbase = wm * 32;

    int st_r = tid >> 4, st_c2 = (tid & 15) * 2;
    int v_hd = tid & 63, v_kp = tid >> 6;
    int v_x = (v_hd >> 3) & 3;

    float accO[2][8][4];
    #pragma unroll
    for (int i = 0; i < 2; i++)
        #pragma unroll
        for (int j = 0; j < 8; j++)
            #pragma unroll
            for (int l = 0; l < 4; l++) accO[i][j][l] = 0.f;
    float mst[4] = { -1e30f, -1e30f, -1e30f, -1e30f };
    float lst[4] = { 0.f, 0.f, 0.f, 0.f };

    for (int j = 0; j < 16; j++) {
        float acc[2][2][4];
        #pragma unroll
        for (int i = 0; i < 2; i++)
            #pragma unroll
            for (int jj = 0; jj < 2; jj++)
                #pragma unroll
                for (int l = 0; l < 4; l++) acc[i][jj][l] = 0.f;

        // ---- scores over D in 4 chunks ----
        for (int dc = 0; dc < 4; dc++) {
            __syncthreads();
            #pragma unroll
            for (int f = 0; f < 4; f++) {
                int r = st_r + f * 16;
                float4 qv = *(const float4*)&Qb[(long)(q0 + r) * C2 + dc * 64 + (tid & 15) * 4];
                Qs[r * 36 + st_c2]     = pack2(qv.x * 0.0625f, qv.y * 0.0625f);
                Qs[r * 36 + st_c2 + 1] = pack2(qv.z * 0.0625f, qv.w * 0.0625f);
                float4 kv = *(const float4*)&Kb[(long)(j * 64 + r) * C2 + dc * 64 + (tid & 15) * 4];
                Ks[r * 36 + st_c2]     = pack2(kv.x, kv.y);
                Ks[r * 36 + st_c2 + 1] = pack2(kv.z, kv.w);
            }
            __syncthreads();
            #pragma unroll
            for (int ks = 0; ks < 4; ks++) {
                int kw = ks * 8;
                uint32_t af[2][4], bf[2][2];
                #pragma unroll
                for (int mt = 0; mt < 2; mt++) {
                    int r = rbase + mt * 16 + g;
                    af[mt][0] = Qs[r * 36 + kw + tig];
                    af[mt][1] = Qs[(r + 8) * 36 + kw + tig];
                    af[mt][2] = Qs[r * 36 + kw + tig + 4];
                    af[mt][3] = Qs[(r + 8) * 36 + kw + tig + 4];
                }
                #pragma unroll
                for (int nt = 0; nt < 2; nt++) {
                    int cN = wn * 16 + nt * 8 + g;
                    bf[nt][0] = Ks[cN * 36 + kw + tig];
                    bf[nt][1] = Ks[cN * 36 + kw + tig + 4];
                }
                #pragma unroll
                for (int mt = 0; mt < 2; mt++)
                    #pragma unroll
                    for (int nt = 0; nt < 2; nt++)
                        MMA16(acc[mt][nt], af[mt][0], af[mt][1], af[mt][2], af[mt][3],
                              bf[nt][0], bf[nt][1]);
            }
        }

        // ---- online softmax ----
        #pragma unroll
        for (int mt = 0; mt < 2; mt++)
            #pragma unroll
            for (int hh = 0; hh < 2; hh++) {
                float mx = -1e30f;
                #pragma unroll
                for (int nt = 0; nt < 2; nt++) {
                    mx = fmaxf(mx, acc[mt][nt][hh * 2]);
                    mx = fmaxf(mx, acc[mt][nt][hh * 2 + 1]);
                }
                mx = fmaxf(mx, __shfl_xor_sync(0xffffffffu, mx, 1));
                mx = fmaxf(mx, __shfl_xor_sync(0xffffffffu, mx, 2));
                if (tig == 0) redm[wn * 64 + rbase + mt * 16 + hh * 8 + g] = mx;
            }
        __syncthreads();

        #pragma unroll
        for (int mt = 0; mt < 2; mt++)
            #pragma unroll
            for (int hh = 0; hh < 2; hh++) {
                int i = mt * 2 + hh;
                int rloc = rbase + mt * 16 + hh * 8 + g;
                float mch = fmaxf(fmaxf(redm[rloc], redm[64 + rloc]),
                                  fmaxf(redm[128 + rloc], redm[192 + rloc]));
                float mnew = fmaxf(mst[i], mch);
                float corr = __expf(mst[i] - mnew);
                mst[i] = mnew;
                float s = 0.f;
                #pragma unroll
                for (int nt = 0; nt < 2; nt++) {
                    float p0 = __expf(acc[mt][nt][hh * 2]     - mnew);
                    float p1 = __expf(acc[mt][nt][hh * 2 + 1] - mnew);
                    s += p0 + p1;
                    Ps[rloc * 36 + wn * 8 + nt * 4 + tig] = pack2(p0, p1);
                }
                s += __shfl_xor_sync(0xffffffffu, s, 1);
                s += __shfl_xor_sync(0xffffffffu, s, 2);
                if (tig == 0) redl[wn * 64 + rloc] = s;
                lst[i] *= corr;
                #pragma unroll
                for (int nt = 0; nt < 8; nt++) {
                    accO[mt][nt][hh * 2]     *= corr;
                    accO[mt][nt][hh * 2 + 1] *= corr;
                }
            }
        __syncthreads();
        #pragma unroll
        for (int mt = 0; mt < 2; mt++)
            #pragma unroll
            for (int hh = 0; hh < 2; hh++) {
                int rloc = rbase + mt * 16 + hh * 8 + g;
                lst[mt * 2 + hh] += redl[rloc] + redl[64 + rloc]
                                  + redl[128 + rloc] + redl[192 + rloc];
            }

        // ---- O += P V over D in 4 chunks ----
        for (int dc = 0; dc < 4; dc++) {
            __syncthreads();
            #pragma unroll
            for (int it = 0; it < 2; it++) {
                int keyp = v_kp + 4 * it;
                long o0 = (long)(j * 64 + 2 * keyp) * C2 + dc * 64 + v_hd;
                float f0 = Vb[o0], f1 = Vb[o0 + C2];
                VT[v_hd * 36 + (keyp ^ v_x)] = pack2(f0, f1);
                keyp += 8;
                long o1 = (long)(j * 64 + 2 * keyp) * C2 + dc * 64 + v_hd;
                f0 = Vb[o1]; f1 = Vb[o1 + C2];
                VT[v_hd * 36 + (keyp ^ v_x)] = pack2(f0, f1);
                keyp += 8;
                long o2 = (long)(j * 64 + 2 * keyp) * C2 + dc * 64 + v_hd;
                f0 = Vb[o2]; f1 = Vb[o2 + C2];
                VT[v_hd * 36 + (keyp ^ v_x)] = pack2(f0, f1);
                keyp += 8;
                long o3 = (long)(j * 64 + 2 * keyp) * C2 + dc * 64 + v_hd;
                f0 = Vb[o3]; f1 = Vb[o3 + C2];
                VT[v_hd * 36 + (keyp ^ v_x)] = pack2(f0, f1);
            }
            __syncthreads();
            #pragma unroll
            for (int ks = 0; ks < 4; ks++) {
                int kw = ks * 8;
                uint32_t af[2][4], bf[2][2];
                #pragma unroll
                for (int mt = 0; mt < 2; mt++) {
                    int r = rbase + mt * 16 + g;
                    af[mt][0] = Ps[r * 36 + kw + tig];
                    af[mt][1] = Ps[(r + 8) * 36 + kw + tig];
                    af[mt][2] = Ps[r * 36 + kw + tig + 4];
                    af[mt][3] = Ps[(r + 8) * 36 + kw + tig + 4];
                }
                #pragma unroll
                for (int nt = 0; nt < 2; nt++) {
                    int cN = wn * 16 + nt * 8 + g;
                    int xc = (cN >> 3) & 3;
                    int w0 = (kw + tig) ^ xc;
                    bf[nt][0] = VT[cN * 36 + w0];
                    bf[nt][1] = VT[cN * 36 + w0 + 4];
                }
                #pragma unroll
                for (int mt = 0; mt < 2; mt++)
                    #pragma unroll
                    for (int nt = 0; nt < 2; nt++)
                        MMA16(accO[mt][dc * 2 + nt], af[mt][0], af[mt][1], af[mt][2], af[mt][3],
                              bf[nt][0], bf[nt][1]);
            }
        }
    }

    #pragma unroll
    for (int mt = 0; mt < 2; mt++) {
        float inv0 = 1.0f / lst[mt * 2];
        float inv1 = 1.0f / lst[mt * 2 + 1];
        #pragma unroll
        for (int u = 0; u < 8; u++) {
            int dc = u >> 1, nt = u & 1;
            int r = q0 + rbase + mt * 16 + g;
            int c = dc * 64 + wn * 16 + nt * 8 + 2 * tig;
            *(float2*)&Ob[(long)r * 1024 + c] =
                make_float2(accO[mt][u][0] * inv0, accO[mt][u][1] * inv0);
            *(float2*)&Ob[(long)(r + 8) * 1024 + c] =
                make_float2(accO[mt][u][2] * inv1, accO[mt][u][3] * inv1);
        }
    }
}

// ---------------- conv 1x1 (512 -> 64) + SiLU ----------------
__global__ void conv1_silu(const float* __restrict__ x, const float* __restrict__ w,
                           const float* __restrict__ bias, float* __restrict__ y) {
    __shared__ float ws[8 * 512];
    int tid = threadIdx.x;
    int o0 = blockIdx.y * 8, b = blockIdx.z;
    for (int i = tid; i < 8 * 512; i += 256) ws[i] = w[(long)o0 * 512 + i];
    __syncthreads();
    int s = blockIdx.x * 256 + tid;
    float acc[8];
    #pragma unroll
    for (int oo = 0; oo < 8; oo++) acc[oo] = bias[o0 + oo];
    const float* xb = x + (long)b * CCH * SS + s;
    for (int c = 0; c < 512; c++) {
        float xv = xb[(long)c * SS];
        #pragma unroll
        for (int oo = 0; oo < 8; oo++) acc[oo] += xv * ws[oo * 512 + c];
    }
    #pragma unroll
    for (int oo = 0; oo < 8; oo++)
        y[(long)b * C8 * SS + (long)(o0 + oo) * SS + s] = silu_f(acc[oo]);
}

// ---------------- conv 3x3 (64 -> 64, SAME) + SiLU ----------------
__global__ void conv2_silu(const float* __restrict__ x, const float* __restrict__ w,
                           const float* __restrict__ bias, float* __restrict__ y) {
    __shared__ float ws[8 * 576];
    int tid = threadIdx.x;
    int o0 = blockIdx.y * 8, b = blockIdx.z;
    for (int i = tid; i < 8 * 576; i += 256) ws[i] = w[(long)o0 * 576 + i];
    __syncthreads();
    int s = blockIdx.x * 256 + tid;
    int yy = s >> 5, xx = s & 31;
    float acc[8];
    #pragma unroll
    for (int oo = 0; oo < 8; oo++) acc[oo] = bias[o0 + oo];
    const float* xb = x + (long)b * C8 * SS;
    for (int ci = 0; ci < 64; ci++) {
        #pragma unroll
        for (int ky = 0; ky < 3; ky++) {
            int py = yy + ky - 1;
            if (py < 0 || py >= 32) continue;
            #pragma unroll
            for (int kx = 0; kx < 3; kx++) {
                int px = xx + kx - 1;
                if (px < 0 || px >= 32) continue;
                float av = xb[(long)ci * SS + py * 32 + px];
                #pragma unroll
                for (int oo = 0; oo < 8; oo++)
                    acc[oo] += av * ws[oo * 576 + ci * 9 + ky * 3 + kx];
            }
        }
    }
    #pragma unroll
    for (int oo = 0; oo < 8; oo++)
        y[(long)b * C8 * SS + (long)(o0 + oo) * SS + s] = silu_f(acc[oo]);
}

// ---------------- conv 1x1 (64 -> 1) + sigmoid ----------------
__global__ void conv3_sig(const float* __restrict__ x, const float* __restrict__ w,
                          const float* __restrict__ bias, float* __restrict__ y) {
    int idx = blockIdx.x * 256 + threadIdx.x;
    int b = idx >> 10, s = idx & 1023;
    float acc = bias[0];
    const float* xb = x + (long)b * C8 * SS + s;
    #pragma unroll 8
    for (int i = 0; i < 64; i++) acc += xb[(long)i * SS] * w[i];
    y[idx] = 1.0f / (1.0f + expf(-acc));
}

// ---------------- spatial_enhanced = hs * sw ----------------
__global__ void senh_mul(const float* __restrict__ hs, const float* __restrict__ sw,
                         float* __restrict__ y) {
    long idx = (long)blockIdx.x * 256 + threadIdx.x;
    int b = (int)(idx >> 19);
    int s = (int)(idx & 1023);
    y[idx] = hs[idx] * sw[b * 1024 + s];
}

// ---------------- launch ----------------
static float* sym(const void* s) { void* p = nullptr; cudaGetSymbolAddress(&p, s); return (float*)p; }

extern "C" void kernel_launch(void* const* d_in, const int* in_sizes, int n_in,
                              void* d_out, int out_size) {
    (void)in_sizes; (void)n_in; (void)out_size;
    const float* x      = (const float*)d_in[0];
    const float* pre_g  = (const float*)d_in[1];
    const float* pre_b  = (const float*)d_in[2];
    const float* norm_g = (const float*)d_in[3];
    const float* norm_b = (const float*)d_in[4];
    const float* post_g = (const float*)d_in[5];
    const float* post_b = (const float*)d_in[6];
    const float* pos    = (const float*)d_in[7];
    const float* sa_w1  = (const float*)d_in[8];
    const float* sa_b1  = (const float*)d_in[9];
    const float* sa_w2  = (const float*)d_in[10];
    const float* sa_b2  = (const float*)d_in[11];
    const float* sa_w3  = (const float*)d_in[12];
    const float* sa_b3  = (const float*)d_in[13];
    const float* wq     = (const float*)d_in[14];
    const float* wk     = (const float*)d_in[15];
    const float* wv     = (const float*)d_in[16];
    const float* wq0    = (const float*)d_in[17];
    const float* wk0    = (const float*)d_in[18];
    const float* wv0    = (const float*)d_in[19];
    const float* wq1    = (const float*)d_in[20];
    const float* wk1    = (const float*)d_in[21];
    const float* wv1    = (const float*)d_in[22];
    const float* ff_w1  = (const float*)d_in[23];
    const float* ff_b1  = (const float*)d_in[24];
    const float* ff_w2  = (const float*)d_in[25];
    const float* ff_b2  = (const float*)d_in[26];
    const float* out_w  = (const float*)d_in[27];
    const float* out_b  = (const float*)d_in[28];
    float* out = (float*)d_out;

    float *hs = sym(d_hs), *shn = sym(d_shn), *senh = sym(d_senh);
    float *a1 = sym(d_a1), *a2 = sym(d_a2), *sw = sym(d_swt);
    float *q = sym(d_q), *k = sym(d_k), *v = sym(d_v);
    float *qm = sym(d_qm), *km = sym(d_km), *vm = sym(d_vm);
    float *comb = sym(d_comb), *f1 = sym(d_f1), *fus = sym(d_fus), *fin = sym(d_fin);

    const int fsSmem = FS_WORDS * 4;
    const int fmSmem = FM_WORDS * 4;
    cudaFuncSetAttribute(flash_std, cudaFuncAttributeMaxDynamicSharedMemorySize, fsSmem);
    cudaFuncSetAttribute(flash_multi, cudaFuncAttributeMaxDynamicSharedMemorySize, fmSmem);

    gn_cmajor<<<BATCH * NGR, 256>>>(x, pre_g, pre_b, pos, hs);
    conv1_silu<<<dim3(4, 8, BATCH), 256>>>(hs, sa_w1, sa_b1, a1);
    conv2_silu<<<dim3(4, 8, BATCH), 256>>>(a1, sa_w2, sa_b2, a2);
    conv3_sig<<<BATCH * SS / 256, 256>>>(a2, sa_w3, sa_b3, sw);
    senh_mul<<<BATCH * CCH * SS / 256, 256>>>(hs, sw, senh);
    gn_cmajor<<<BATCH * NGR, 256>>>(hs, norm_g, norm_b, nullptr, shn);

    // QKV projections (one launch)
    Ptr6 pq = {};
    pq.A[0] = shn; pq.A[1] = shn; pq.A[2] = shn;
    pq.W[0] = wq;  pq.W[1] = wk;  pq.W[2] = wv;
    pq.Y[0] = q;   pq.Y[1] = k;   pq.Y[2] = v;
    gemm_proj<<<dim3(8, 8, 24), 256>>>(pq, 512);

    // multi-scale projections (one launch)
    long moff = 8LL * SS * C2;
    Ptr6 pm = {};
    pm.A[0] = senh; pm.A[1] = shn; pm.A[2] = shn;
    pm.A[3] = senh; pm.A[4] = shn; pm.A[5] = shn;
    pm.W[0] = wq0;  pm.W[1] = wk0; pm.W[2] = wv0;
    pm.W[3] = wq1;  pm.W[4] = wk1; pm.W[5] = wv1;
    pm.Y[0] = qm;        pm.Y[1] = km;        pm.Y[2] = vm;
    pm.Y[3] = qm + moff; pm.Y[4] = km + moff; pm.Y[5] = vm + moff;
    gemm_proj<<<dim3(8, 4, 48), 256>>>(pm, 256);

    // std MHA flash -> comb[:, :, 0:512]
    flash_std<<<dim3(8, 1, BATCH * NHD), 256, fsSmem>>>(q, k, v, comb);
    // multi-scale flash -> comb[:, :, 512:1024]
    flash_multi<<<dim3(16, 1, 16), 256, fmSmem>>>(qm, km, vm, comb);

    // ff1 (silu)
    gemm_nt<<<dim3(8, 8, BATCH), 256>>>(comb, (long)SS * 2 * CCH, ff_w1, ff_b1,
                                        f1, (long)SS * CCH, 2 * CCH, 2 * CCH, 2 * CCH, CCH, 1);
    // ff2
    gemm_nt<<<dim3(8, 8, BATCH), 256>>>(f1, (long)SS * CCH, ff_w2, ff_b2,
                                        fus, (long)SS * CCH, CCH, CCH, CCH, CCH, 0);
    // out proj
    gemm_nt<<<dim3(8, 8, BATCH), 256>>>(fus, (long)SS * CCH, out_w, out_b,
                                        fin, (long)SS * CCH, CCH, CCH, CCH, CCH, 0);
    // post GN + residual
    gn_post_k<<<BATCH * NGR, 256>>>(fin, post_g, post_b, x, out);
}